// round 13
// baseline (speedup 1.0000x reference)
#include <cuda_runtime.h>
#include <cuda_fp16.h>
#include <mma.h>
#include <cstdint>

using namespace nvcuda;

#define NN    10000
#define EE    320000
#define ET    330000
#define GG    100
#define CHN   250
#define HOUT  125
#define SLOPE 0.2f

#define MT2   64        // GEMM M tile
#define NT    256
#define MPAD  10112     // 158 * 64
#define KP1   384
#define KP2   256

// ---------------- scratch (zero-initialized at module load) --------------------
__device__ __half g_hh[MPAD * 256];          // GEMM output fp16 (gather source)
__device__ __half g_a2h[MPAD * 256];         // layers 2-4 A input fp16 (pad rows stay 0)
__device__ float  g_fa[NN * CHN];            // layer-4 output fp32 (pool source)
__device__ float4 g_att0[NN];
__device__ float2 g_att1[NN];
__device__ int    g_cnt[NN];                 // zeroed at load; re-zeroed by scan_kernel
__device__ int    g_off[NN + 1];
__device__ int    g_pos[NN];
__device__ int    g_csr[ET];
__device__ __align__(256) __half g_a1h[MPAD * KP1];
#define WOFF1 (NT * KP1)
#define WTOTAL (NT * KP1 + 3 * NT * KP2)
__device__ __align__(256) __half g_wh[WTOTAL];

// ---------------- helpers ------------------------------------------------------
__device__ __forceinline__ uint32_t smem_u32(const void* p) {
    uint32_t a;
    asm("{ .reg .u64 t; cvta.to.shared.u64 t, %1; cvt.u32.u64 %0, t; }" : "=r"(a) : "l"(p));
    return a;
}
__device__ __forceinline__ void cp_async16(uint32_t dst, const void* src) {
    asm volatile("cp.async.cg.shared.global [%0], [%1], 16;" :: "r"(dst), "l"(src));
}
__device__ __forceinline__ void cp_commit() { asm volatile("cp.async.commit_group;" ::: "memory"); }
__device__ __forceinline__ void cp_wait2()  { asm volatile("cp.async.wait_group 2;" ::: "memory"); }
__device__ __forceinline__ float leaky(float x) { return x > 0.f ? x : SLOPE * x; }

// ---------------- fused: fp32->fp16 A split + degree count ---------------------
__global__ void split_a_count_kernel(const float* __restrict__ in,
                                     const int* __restrict__ ei)
{
    int i = blockIdx.x * blockDim.x + threadIdx.x;
    if (i < ET) {
        int dst = (i < EE) ? ei[EE + i] : (i - EE);
        atomicAdd(&g_cnt[dst], 1);
    }
    if (i < MPAD * KP1) {
        int r = i / KP1, k = i - r * KP1;
        float v = (r < NN && k < 336) ? in[(size_t)r * 336 + k] : 0.f;
        g_a1h[i] = __float2half(v);
    }
}

// ---------------- scan (also re-zeroes g_cnt for the next graph replay) --------
__global__ void scan_kernel() {
    __shared__ int sp[1024];
    int t = threadIdx.x;
    int base = t * 10;
    int loc[10];
    int sum = 0;
#pragma unroll
    for (int i = 0; i < 10; i++) {
        int idx = base + i;
        int v = 0;
        if (idx < NN) { v = g_cnt[idx]; g_cnt[idx] = 0; }
        loc[i] = sum; sum += v;
    }
    sp[t] = sum;
    __syncthreads();
    for (int off = 1; off < 1024; off <<= 1) {
        int v = (t >= off) ? sp[t - off] : 0;
        __syncthreads();
        sp[t] += v;
        __syncthreads();
    }
    int pre = sp[t] - sum;
#pragma unroll
    for (int i = 0; i < 10; i++) {
        int idx = base + i;
        if (idx < NN) { int o = pre + loc[i]; g_off[idx] = o; g_pos[idx] = o; }
    }
    if (t == 1023) g_off[NN] = sp[1023];
}

// ---------------- fused: W fp16 pack + CSR scatter -------------------------------
__global__ void split_w_scatter_kernel(const float* __restrict__ W1, const float* __restrict__ W2,
                                       const float* __restrict__ W3, const float* __restrict__ W4,
                                       const int* __restrict__ ei)
{
    int idx = blockIdx.x * blockDim.x + threadIdx.x;
    if (idx < ET) {
        int src, dst;
        if (idx < EE) { src = ei[idx]; dst = ei[EE + idx]; }
        else          { src = idx - EE; dst = idx - EE; }
        int p = atomicAdd(&g_pos[dst], 1);
        g_csr[p] = src;
    }
    if (idx < WTOTAL) {
        const float* W; int K, Kpad, rem;
        if (idx < NT * KP1) { W = W1; K = 336; Kpad = KP1; rem = idx; }
        else {
            int idx2 = idx - NT * KP1;
            int l = idx2 / (NT * KP2);
            rem = idx2 - l * (NT * KP2);
            W = (l == 0) ? W2 : (l == 1) ? W3 : W4;
            K = 250; Kpad = KP2;
        }
        int n = rem / Kpad, k = rem - n * Kpad;
        float v = (n < CHN && k < K) ? W[(size_t)k * CHN + n] : 0.f;
        g_wh[idx] = __float2half(v);
    }
}

// ---------------- WMMA fp16 GEMM: 64x128 tile, K' = Kpad ------------------------
#define ALD   40
#define BLD   40
#define A_ELE (64 * ALD)
#define B_ELE (128 * BLD)
#define STG_ELE (A_ELE + B_ELE)   // 7680 halves = 15360 B
#define CLD   136
#define GEMM_SMEM (4 * STG_ELE * 2)

__global__ __launch_bounds__(256) void gemm_wmma_kernel(
    const __half* __restrict__ Ain, const __half* __restrict__ Bin,
    int Kpad,
    const float* __restrict__ asrc, const float* __restrict__ adst,
    __half* __restrict__ hout)
{
    extern __shared__ char smem[];
    float* Cs = (float*)smem;
    __shared__ float s_as[128], s_ad[128];

    int tid = threadIdx.x;
    int wid = tid >> 5;
    int wm = wid >> 2, wn = wid & 3;
    int m0 = blockIdx.x * MT2;
    int by = blockIdx.y;
    int n0 = by * 128;

    if (tid < 128) {
        int col = n0 + tid;
        s_as[tid] = (col < CHN) ? asrc[col] : 0.f;
        s_ad[tid] = (col < CHN) ? adst[col] : 0.f;
    }

    uint32_t sbase = smem_u32(smem);
    int niter = Kpad >> 5;           // 12 (l1) / 8 (l2-4)

    auto load_stage = [&](int st, int kb) {
        int kk = kb << 5;
        uint32_t stb = sbase + st * STG_ELE * 2;
        {
            int rowa = tid >> 2, grpa = tid & 3;
            cp_async16(stb + (rowa * ALD + grpa * 8) * 2,
                       Ain + (size_t)(m0 + rowa) * Kpad + kk + grpa * 8);
        }
#pragma unroll
        for (int i = 0; i < 2; i++) {
            int c = tid + i * 256;
            int rowb = c >> 2, grpb = c & 3;
            cp_async16(stb + (A_ELE + rowb * BLD + grpb * 8) * 2,
                       Bin + (size_t)(n0 + rowb) * Kpad + kk + grpb * 8);
        }
        cp_commit();
    };

    wmma::fragment<wmma::accumulator, 16, 16, 16, float> c[2][2];
#pragma unroll
    for (int i = 0; i < 2; i++)
#pragma unroll
        for (int j = 0; j < 2; j++) wmma::fill_fragment(c[i][j], 0.f);

    load_stage(0, 0);
    load_stage(1, 1);
    load_stage(2, 2);

    for (int kb = 0; kb < niter; kb++) {
        cp_wait2();
        __syncthreads();
        if (kb + 3 < niter) load_stage((kb + 3) & 3, kb + 3);
        else                cp_commit();

        const __half* stg = (const __half*)(smem + (size_t)(kb & 3) * STG_ELE * 2);
        const __half* at = stg + wm * 32 * ALD;
        const __half* bt = stg + A_ELE + wn * 32 * BLD;
#pragma unroll
        for (int ks = 0; ks < 2; ks++) {
            wmma::fragment<wmma::matrix_a, 16, 16, 16, __half, wmma::row_major> a0, a1;
            wmma::load_matrix_sync(a0, at + ks * 16, ALD);
            wmma::load_matrix_sync(a1, at + 16 * ALD + ks * 16, ALD);
            wmma::fragment<wmma::matrix_b, 16, 16, 16, __half, wmma::col_major> b0, b1;
            wmma::load_matrix_sync(b0, bt + ks * 16, BLD);
            wmma::load_matrix_sync(b1, bt + 16 * BLD + ks * 16, BLD);
            wmma::mma_sync(c[0][0], a0, b0, c[0][0]);
            wmma::mma_sync(c[0][1], a0, b1, c[0][1]);
            wmma::mma_sync(c[1][0], a1, b0, c[1][0]);
            wmma::mma_sync(c[1][1], a1, b1, c[1][1]);
        }
    }
    __syncthreads();

#pragma unroll
    for (int i = 0; i < 2; i++)
#pragma unroll
        for (int j = 0; j < 2; j++)
            wmma::store_matrix_sync(Cs + (wm * 32 + i * 16) * CLD + wn * 32 + j * 16,
                                    c[i][j], CLD, wmma::mem_row_major);
    __syncthreads();

    // coalesced fp16 store (stride 256)
#pragma unroll
    for (int it = 0; it < 16; it++) {
        int idx = it * 256 + tid;
        int r = idx >> 6, c2 = idx & 63;
        int grow = m0 + r, gcol = n0 + 2 * c2;
        if (grow < NN && gcol < CHN) {
            float v0 = Cs[r * CLD + 2 * c2];
            float v1 = Cs[r * CLD + 2 * c2 + 1];
            *(__half2*)(hout + (size_t)grow * 256 + gcol) = __floats2half2_rn(v0, v1);
        }
    }

    // fused attention dots
    if (tid < 128) {
        int r = tid >> 1;
        int half = tid & 1;
        int ccb = half * 64;
        float s0 = 0.f, d0 = 0.f, s1 = 0.f, d1 = 0.f;
#pragma unroll 8
        for (int q = 0; q < 64; q++) {
            int cc = ccb + q;
            float v = Cs[r * CLD + cc];
            float a = s_as[cc], bvd = s_ad[cc];
            if (n0 + cc < HOUT) { s0 += v * a; d0 += v * bvd; }
            else                { s1 += v * a; d1 += v * bvd; }
        }
        s0 += __shfl_xor_sync(0xffffffffu, s0, 1);
        d0 += __shfl_xor_sync(0xffffffffu, d0, 1);
        s1 += __shfl_xor_sync(0xffffffffu, s1, 1);
        d1 += __shfl_xor_sync(0xffffffffu, d1, 1);
        int grow = m0 + r;
        if (half == 0 && grow < NN) {
            if (by == 0) g_att0[grow] = make_float4(s0, d0, s1, d1);
            else         g_att1[grow] = make_float2(s1, d1);
        }
    }
}

// ---------------- aggregation: single-pass softmax + fp16 gather ----------------
__global__ __launch_bounds__(128) void agg_kernel(const float* __restrict__ bias,
                                                  __half* __restrict__ oh,
                                                  float* __restrict__ of32,
                                                  int f32out)
{
    int i = blockIdx.x;
    int tid = threadIdx.x;
    int lane = tid & 31, warp = tid >> 5;

    __shared__ float w0[4], w1[4];
    __shared__ int   s_src[128];
    __shared__ float s_a0[128], s_a1[128];

    int s = g_off[i], e = g_off[i + 1];
    int d = e - s;
    float4 a0i = g_att0[i];
    float2 a1i = g_att1[i];
    float ed0 = a0i.y, ed1 = a0i.w + a1i.y;

    float acc0 = 0.f, acc1 = 0.f;
    int c0 = 2 * tid;
    bool act = (tid < HOUT);
    bool head0a = (c0 < HOUT);
    bool head0b = (c0 + 1 < HOUT);

    if (d <= 128) {
        bool valid = tid < d;
        int src = 0;
        float l0 = -1e30f, l1 = -1e30f;
        if (valid) {
            src = g_csr[s + tid];
            float4 b0 = g_att0[src]; float2 b1 = g_att1[src];
            l0 = leaky(b0.x + ed0);
            l1 = leaky(b0.z + b1.x + ed1);
        }
        float m0 = l0, m1 = l1;
#pragma unroll
        for (int o = 16; o; o >>= 1) {
            m0 = fmaxf(m0, __shfl_xor_sync(0xffffffffu, m0, o));
            m1 = fmaxf(m1, __shfl_xor_sync(0xffffffffu, m1, o));
        }
        if (lane == 0) { w0[warp] = m0; w1[warp] = m1; }
        __syncthreads();
        m0 = fmaxf(fmaxf(w0[0], w0[1]), fmaxf(w0[2], w0[3]));
        m1 = fmaxf(fmaxf(w1[0], w1[1]), fmaxf(w1[2], w1[3]));
        __syncthreads();

        float p0 = valid ? __expf(l0 - m0) : 0.f;
        float p1 = valid ? __expf(l1 - m1) : 0.f;
        float d0 = p0, d1 = p1;
#pragma unroll
        for (int o = 16; o; o >>= 1) {
            d0 += __shfl_xor_sync(0xffffffffu, d0, o);
            d1 += __shfl_xor_sync(0xffffffffu, d1, o);
        }
        if (lane == 0) { w0[warp] = d0; w1[warp] = d1; }
        __syncthreads();
        d0 = w0[0] + w0[1] + w0[2] + w0[3] + 1e-16f;
        d1 = w1[0] + w1[1] + w1[2] + w1[3] + 1e-16f;
        float r0 = 1.0f / d0, r1 = 1.0f / d1;

        s_src[tid] = src;
        s_a0[tid] = p0 * r0;
        s_a1[tid] = p1 * r1;
        __syncthreads();

        if (act) {
#pragma unroll 4
            for (int k = 0; k < d; k++) {
                int sk = s_src[k];
                __half2 hv2 = *(const __half2*)(g_hh + (size_t)sk * 256 + c0);
                float2 hv = __half22float2(hv2);
                float aa = head0a ? s_a0[k] : s_a1[k];
                float ab = head0b ? s_a0[k] : s_a1[k];
                acc0 += aa * hv.x;
                acc1 += ab * hv.y;
            }
        }
    } else {
        float m0 = -1e30f, m1 = -1e30f;
        for (int j = s + tid; j < e; j += 128) {
            int src = g_csr[j];
            float4 b0 = g_att0[src]; float2 b1 = g_att1[src];
            m0 = fmaxf(m0, leaky(b0.x + ed0));
            m1 = fmaxf(m1, leaky(b0.z + b1.x + ed1));
        }
#pragma unroll
        for (int o = 16; o; o >>= 1) {
            m0 = fmaxf(m0, __shfl_xor_sync(0xffffffffu, m0, o));
            m1 = fmaxf(m1, __shfl_xor_sync(0xffffffffu, m1, o));
        }
        if (lane == 0) { w0[warp] = m0; w1[warp] = m1; }
        __syncthreads();
        m0 = fmaxf(fmaxf(w0[0], w0[1]), fmaxf(w0[2], w0[3]));
        m1 = fmaxf(fmaxf(w1[0], w1[1]), fmaxf(w1[2], w1[3]));
        __syncthreads();

        float d0 = 0.f, d1 = 0.f;
        for (int j = s + tid; j < e; j += 128) {
            int src = g_csr[j];
            float4 b0 = g_att0[src]; float2 b1 = g_att1[src];
            d0 += __expf(leaky(b0.x + ed0) - m0);
            d1 += __expf(leaky(b0.z + b1.x + ed1) - m1);
        }
#pragma unroll
        for (int o = 16; o; o >>= 1) {
            d0 += __shfl_xor_sync(0xffffffffu, d0, o);
            d1 += __shfl_xor_sync(0xffffffffu, d1, o);
        }
        if (lane == 0) { w0[warp] = d0; w1[warp] = d1; }
        __syncthreads();
        d0 = w0[0] + w0[1] + w0[2] + w0[3] + 1e-16f;
        d1 = w1[0] + w1[1] + w1[2] + w1[3] + 1e-16f;
        float r0 = 1.0f / d0, r1 = 1.0f / d1;

        for (int base = s; base < e; base += 128) {
            int j = base + tid;
            if (j < e) {
                int src = g_csr[j];
                float4 b0 = g_att0[src]; float2 b1 = g_att1[src];
                s_src[tid] = src;
                s_a0[tid] = __expf(leaky(b0.x + ed0) - m0) * r0;
                s_a1[tid] = __expf(leaky(b0.z + b1.x + ed1) - m1) * r1;
            }
            __syncthreads();
            int cnt = min(128, e - base);
            if (act) {
#pragma unroll 4
                for (int k = 0; k < cnt; k++) {
                    int sk = s_src[k];
                    __half2 hv2 = *(const __half2*)(g_hh + (size_t)sk * 256 + c0);
                    float2 hv = __half22float2(hv2);
                    float aa = head0a ? s_a0[k] : s_a1[k];
                    float ab = head0b ? s_a0[k] : s_a1[k];
                    acc0 += aa * hv.x;
                    acc1 += ab * hv.y;
                }
            }
            __syncthreads();
        }
    }

    if (f32out) {
        if (act) {
            float v0 = fmaxf(acc0 + bias[c0], 0.f);
            float v1 = fmaxf(acc1 + bias[c0 + 1], 0.f);
            of32[(size_t)i * CHN + c0]     = v0;
            of32[(size_t)i * CHN + c0 + 1] = v1;
        }
    } else {
        size_t o = (size_t)i * KP2 + c0;
        if (act) {
            float v0 = fmaxf(acc0 + bias[c0], 0.f);
            float v1 = fmaxf(acc1 + bias[c0 + 1], 0.f);
            *(__half2*)(oh + o) = __floats2half2_rn(v0, v1);
        } else {
            *(__half2*)(oh + o) = __floats2half2_rn(0.f, 0.f);
        }
    }
}

// ---------------- fused pool + 4-layer MLP (one block per graph) ---------------
__global__ __launch_bounds__(256) void pool_mlp_kernel(
    const int* __restrict__ batch, const float* __restrict__ feat,
    const float* __restrict__ lw1, const float* __restrict__ lb1,
    const float* __restrict__ lw2, const float* __restrict__ lb2,
    const float* __restrict__ lw3, const float* __restrict__ lb3,
    const float* __restrict__ lw4, const float* __restrict__ lb4,
    float* __restrict__ out)
{
    int g = blockIdx.x;
    int tid = threadIdx.x;
    __shared__ int ss, se;
    __shared__ float sg[CHN], t1[200], t2[100], t3[100];

    if (tid == 0) {
        int lo = 0, hi = NN;
        while (lo < hi) { int mid = (lo + hi) >> 1; if (batch[mid] < g) lo = mid + 1; else hi = mid; }
        ss = lo;
        lo = 0; hi = NN;
        while (lo < hi) { int mid = (lo + hi) >> 1; if (batch[mid] < g + 1) lo = mid + 1; else hi = mid; }
        se = lo;
    }
    __syncthreads();
    if (tid < CHN) {
        float sum = 0.f;
        for (int i = ss; i < se; i++) sum += feat[(size_t)i * CHN + tid];
        sg[tid] = sum / fmaxf((float)(se - ss), 1.0f);
    }
    __syncthreads();
    if (tid < 200) {
        float s = lb1[tid];
        for (int k = 0; k < 250; k++) s += sg[k] * lw1[k * 200 + tid];
        t1[tid] = fmaxf(s, 0.f);
    }
    __syncthreads();
    if (tid < 100) {
        float s = lb2[tid];
        for (int k = 0; k < 200; k++) s += t1[k] * lw2[k * 100 + tid];
        t2[tid] = fmaxf(s, 0.f);
    }
    __syncthreads();
    if (tid < 100) {
        float s = lb3[tid];
        for (int k = 0; k < 100; k++) s += t2[k] * lw3[k * 100 + tid];
        t3[tid] = fmaxf(s, 0.f);
    }
    __syncthreads();
    if (tid < 29) {
        float s = lb4[tid];
        for (int k = 0; k < 100; k++) s += t3[k] * lw4[k * 29 + tid];
        out[g * 29 + tid] = s;
    }
}

// ---------------- driver --------------------------------------------------------
extern "C" void kernel_launch(void* const* d_in, const int* in_sizes, int n_in,
                              void* d_out, int out_size)
{
    const float* x     = (const float*)d_in[0];
    const int*   ei    = (const int*)d_in[1];
    const int*   batch = (const int*)d_in[2];
    const float* W[4]    = {(const float*)d_in[3],  (const float*)d_in[7],
                            (const float*)d_in[11], (const float*)d_in[15]};
    const float* Asrc[4] = {(const float*)d_in[4],  (const float*)d_in[8],
                            (const float*)d_in[12], (const float*)d_in[16]};
    const float* Adst[4] = {(const float*)d_in[5],  (const float*)d_in[9],
                            (const float*)d_in[13], (const float*)d_in[17]};
    const float* Bb[4]   = {(const float*)d_in[6],  (const float*)d_in[10],
                            (const float*)d_in[14], (const float*)d_in[18]};
    const float* lw1 = (const float*)d_in[19]; const float* lb1 = (const float*)d_in[20];
    const float* lw2 = (const float*)d_in[21]; const float* lb2 = (const float*)d_in[22];
    const float* lw3 = (const float*)d_in[23]; const float* lb3 = (const float*)d_in[24];
    const float* lw4 = (const float*)d_in[25]; const float* lb4 = (const float*)d_in[26];
    float* out = (float*)d_out;

    float *faP;
    __half *hhP, *a1hP, *a2hP, *whP;
    cudaGetSymbolAddress((void**)&hhP,  g_hh);
    cudaGetSymbolAddress((void**)&faP,  g_fa);
    cudaGetSymbolAddress((void**)&a1hP, g_a1h);
    cudaGetSymbolAddress((void**)&a2hP, g_a2h);
    cudaGetSymbolAddress((void**)&whP,  g_wh);

    cudaFuncSetAttribute(gemm_wmma_kernel,
                         cudaFuncAttributeMaxDynamicSharedMemorySize, GEMM_SMEM);

    // 3 setup launches (count fused into split_a; scatter fused into split_w;
    // g_cnt re-zeroed inside scan; pad rows rely on static zero-init)
    split_a_count_kernel<<<(MPAD * KP1 + 255) / 256, 256>>>(x, ei);
    scan_kernel<<<1, 1024>>>();
    split_w_scatter_kernel<<<(ET + 255) / 256, 256>>>(W[0], W[1], W[2], W[3], ei);

    dim3 ggrid(MPAD / MT2, 2);
    for (int l = 0; l < 4; l++) {
        const __half* Ain = (l == 0) ? a1hP : a2hP;
        int Kpad = (l == 0) ? KP1 : KP2;
        size_t woff = (l == 0) ? 0 : (size_t)WOFF1 + (size_t)(l - 1) * NT * KP2;
        gemm_wmma_kernel<<<ggrid, 256, GEMM_SMEM>>>(
            Ain, whP + woff, Kpad, Asrc[l], Adst[l], hhP);
        agg_kernel<<<NN, 128>>>(Bb[l], a2hP, faP, (l == 3) ? 1 : 0);
    }

    pool_mlp_kernel<<<GG, 256>>>(batch, faP, lw1, lb1, lw2, lb2, lw3, lb3, lw4, lb4, out);
}

// round 14
// speedup vs baseline: 1.0322x; 1.0322x over previous
#include <cuda_runtime.h>
#include <cuda_fp16.h>
#include <mma.h>
#include <cstdint>

using namespace nvcuda;

#define NN    10000
#define EE    320000
#define ET    330000
#define GG    100
#define CHN   250
#define HOUT  125
#define SLOPE 0.2f

#define MT2   64        // GEMM M tile
#define NT    256
#define MPAD  10112     // 158 * 64
#define KP1   384
#define KP2   256

// ---------------- scratch ------------------------------------------------------
__device__ __half g_hh[MPAD * 256];          // GEMM output fp16 (gather source)
__device__ __half g_a2h[MPAD * 256];         // layers 2-4 A input fp16 (agg-written)
__device__ float  g_fa[NN * CHN];            // layer-4 output fp32 (pool source)
__device__ float4 g_att0[NN];
__device__ float2 g_att1[NN];
__device__ int    g_cnt[NN];
__device__ int    g_off[NN + 1];
__device__ int    g_pos[NN];
__device__ int    g_csr[ET];
__device__ __align__(256) __half g_a1h[MPAD * KP1];
#define WOFF1 (NT * KP1)
#define WTOTAL (NT * KP1 + 3 * NT * KP2)
__device__ __align__(256) __half g_wh[WTOTAL];

// ---------------- helpers ------------------------------------------------------
__device__ __forceinline__ uint32_t smem_u32(const void* p) {
    uint32_t a;
    asm("{ .reg .u64 t; cvta.to.shared.u64 t, %1; cvt.u32.u64 %0, t; }" : "=r"(a) : "l"(p));
    return a;
}
__device__ __forceinline__ void cp_async16(uint32_t dst, const void* src) {
    asm volatile("cp.async.cg.shared.global [%0], [%1], 16;" :: "r"(dst), "l"(src));
}
__device__ __forceinline__ void cp_commit() { asm volatile("cp.async.commit_group;" ::: "memory"); }
__device__ __forceinline__ void cp_wait1()  { asm volatile("cp.async.wait_group 1;" ::: "memory"); }
__device__ __forceinline__ float leaky(float x) { return x > 0.f ? x : SLOPE * x; }

// ---------------- init ----------------------------------------------------------
__global__ void init_kernel() {
    int i = blockIdx.x * blockDim.x + threadIdx.x;
    if (i < NN) g_cnt[i] = 0;
    int p = i - NN;
    if (p >= 0 && p < 112 * KP2) {
        g_a2h[10000 * KP2 + p] = __float2half(0.f);
    }
}
__global__ void count_kernel(const int* __restrict__ ei) {
    int i = blockIdx.x * blockDim.x + threadIdx.x;
    if (i >= ET) return;
    int dst = (i < EE) ? ei[EE + i] : (i - EE);
    atomicAdd(&g_cnt[dst], 1);
}
__global__ void scan_kernel() {
    __shared__ int sp[1024];
    int t = threadIdx.x;
    int base = t * 10;
    int loc[10];
    int sum = 0;
#pragma unroll
    for (int i = 0; i < 10; i++) {
        int idx = base + i;
        int v = (idx < NN) ? g_cnt[idx] : 0;
        loc[i] = sum; sum += v;
    }
    sp[t] = sum;
    __syncthreads();
    for (int off = 1; off < 1024; off <<= 1) {
        int v = (t >= off) ? sp[t - off] : 0;
        __syncthreads();
        sp[t] += v;
        __syncthreads();
    }
    int pre = sp[t] - sum;
#pragma unroll
    for (int i = 0; i < 10; i++) {
        int idx = base + i;
        if (idx < NN) { int o = pre + loc[i]; g_off[idx] = o; g_pos[idx] = o; }
    }
    if (t == 1023) g_off[NN] = sp[1023];
}
__global__ void scatter_kernel(const int* __restrict__ ei) {
    int i = blockIdx.x * blockDim.x + threadIdx.x;
    if (i >= ET) return;
    int src, dst;
    if (i < EE) { src = ei[i]; dst = ei[EE + i]; }
    else        { src = i - EE; dst = i - EE; }
    int p = atomicAdd(&g_pos[dst], 1);
    g_csr[p] = src;
}

// ---------------- splits -------------------------------------------------------
__global__ void split_a_kernel(const float* __restrict__ in) {
    int idx = blockIdx.x * blockDim.x + threadIdx.x;
    if (idx >= MPAD * KP1) return;
    int r = idx / KP1, k = idx - r * KP1;
    float v = (r < NN && k < 336) ? in[(size_t)r * 336 + k] : 0.f;
    g_a1h[idx] = __float2half(v);
}
__global__ void split_w_all_kernel(const float* __restrict__ W1, const float* __restrict__ W2,
                                   const float* __restrict__ W3, const float* __restrict__ W4)
{
    int idx = blockIdx.x * blockDim.x + threadIdx.x;
    if (idx >= WTOTAL) return;
    const float* W; int K, Kpad, rem;
    if (idx < NT * KP1) { W = W1; K = 336; Kpad = KP1; rem = idx; }
    else {
        int idx2 = idx - NT * KP1;
        int l = idx2 / (NT * KP2);
        rem = idx2 - l * (NT * KP2);
        W = (l == 0) ? W2 : (l == 1) ? W3 : W4;
        K = 250; Kpad = KP2;
    }
    int n = rem / Kpad, k = rem - n * Kpad;
    float v = (n < CHN && k < K) ? W[(size_t)k * CHN + n] : 0.f;
    g_wh[idx] = __float2half(v);
}

// ---------------- WMMA fp16 GEMM: 64x128 tile, 3-stage ring, 4 CTAs/SM ----------
#define ALD   40
#define BLD   40
#define A_ELE (64 * ALD)
#define B_ELE (128 * BLD)
#define STG_ELE (A_ELE + B_ELE)   // 7680 halves = 15360 B
#define CLD   136
#define GEMM_SMEM (3 * STG_ELE * 2)   // 46080 B (Cs 64*136*4=34816 fits)

__global__ __launch_bounds__(256, 4) void gemm_wmma_kernel(
    const __half* __restrict__ Ain, const __half* __restrict__ Bin,
    int Kpad,
    const float* __restrict__ asrc, const float* __restrict__ adst,
    __half* __restrict__ hout)
{
    extern __shared__ char smem[];
    float* Cs = (float*)smem;
    __shared__ float s_as[128], s_ad[128];

    int tid = threadIdx.x;
    int wid = tid >> 5;
    int wm = wid >> 2, wn = wid & 3;
    int m0 = blockIdx.x * MT2;
    int by = blockIdx.y;
    int n0 = by * 128;

    if (tid < 128) {
        int col = n0 + tid;
        s_as[tid] = (col < CHN) ? asrc[col] : 0.f;
        s_ad[tid] = (col < CHN) ? adst[col] : 0.f;
    }

    uint32_t sbase = smem_u32(smem);
    int niter = Kpad >> 5;           // 12 (l1) / 8 (l2-4)

    auto load_stage = [&](int st, int kb) {
        int kk = kb << 5;
        uint32_t stb = sbase + st * STG_ELE * 2;
        {
            int rowa = tid >> 2, grpa = tid & 3;
            cp_async16(stb + (rowa * ALD + grpa * 8) * 2,
                       Ain + (size_t)(m0 + rowa) * Kpad + kk + grpa * 8);
        }
#pragma unroll
        for (int i = 0; i < 2; i++) {
            int c = tid + i * 256;
            int rowb = c >> 2, grpb = c & 3;
            cp_async16(stb + (A_ELE + rowb * BLD + grpb * 8) * 2,
                       Bin + (size_t)(n0 + rowb) * Kpad + kk + grpb * 8);
        }
        cp_commit();
    };

    wmma::fragment<wmma::accumulator, 16, 16, 16, float> c[2][2];
#pragma unroll
    for (int i = 0; i < 2; i++)
#pragma unroll
        for (int j = 0; j < 2; j++) wmma::fill_fragment(c[i][j], 0.f);

    // 3-stage ring, prefetch depth 2, single barrier per iteration
    load_stage(0, 0);
    load_stage(1, 1);

    int slot = 0;
    for (int kb = 0; kb < niter; kb++) {
        cp_wait1();            // stage kb complete (1 group may remain pending)
        __syncthreads();       // everyone done reading slot used at kb-1
        int nslot = slot + 2; if (nslot >= 3) nslot -= 3;
        if (kb + 2 < niter) load_stage(nslot, kb + 2);
        else                cp_commit();   // keep group count in lockstep

        const __half* stg = (const __half*)(smem + (size_t)slot * STG_ELE * 2);
        const __half* at = stg + wm * 32 * ALD;
        const __half* bt = stg + A_ELE + wn * 32 * BLD;
#pragma unroll
        for (int ks = 0; ks < 2; ks++) {
            wmma::fragment<wmma::matrix_a, 16, 16, 16, __half, wmma::row_major> a0, a1;
            wmma::load_matrix_sync(a0, at + ks * 16, ALD);
            wmma::load_matrix_sync(a1, at + 16 * ALD + ks * 16, ALD);
            wmma::fragment<wmma::matrix_b, 16, 16, 16, __half, wmma::col_major> b0, b1;
            wmma::load_matrix_sync(b0, bt + ks * 16, BLD);
            wmma::load_matrix_sync(b1, bt + 16 * BLD + ks * 16, BLD);
            wmma::mma_sync(c[0][0], a0, b0, c[0][0]);
            wmma::mma_sync(c[0][1], a0, b1, c[0][1]);
            wmma::mma_sync(c[1][0], a1, b0, c[1][0]);
            wmma::mma_sync(c[1][1], a1, b1, c[1][1]);
        }
        slot = (slot + 1 == 3) ? 0 : slot + 1;
    }
    __syncthreads();

#pragma unroll
    for (int i = 0; i < 2; i++)
#pragma unroll
        for (int j = 0; j < 2; j++)
            wmma::store_matrix_sync(Cs + (wm * 32 + i * 16) * CLD + wn * 32 + j * 16,
                                    c[i][j], CLD, wmma::mem_row_major);
    __syncthreads();

    // coalesced fp16 store (stride 256)
#pragma unroll
    for (int it = 0; it < 16; it++) {
        int idx = it * 256 + tid;
        int r = idx >> 6, c2 = idx & 63;
        int grow = m0 + r, gcol = n0 + 2 * c2;
        if (grow < NN && gcol < CHN) {
            float v0 = Cs[r * CLD + 2 * c2];
            float v1 = Cs[r * CLD + 2 * c2 + 1];
            *(__half2*)(hout + (size_t)grow * 256 + gcol) = __floats2half2_rn(v0, v1);
        }
    }

    // fused attention dots
    if (tid < 128) {
        int r = tid >> 1;
        int half = tid & 1;
        int ccb = half * 64;
        float s0 = 0.f, d0 = 0.f, s1 = 0.f, d1 = 0.f;
#pragma unroll 8
        for (int q = 0; q < 64; q++) {
            int cc = ccb + q;
            float v = Cs[r * CLD + cc];
            float a = s_as[cc], bvd = s_ad[cc];
            if (n0 + cc < HOUT) { s0 += v * a; d0 += v * bvd; }
            else                { s1 += v * a; d1 += v * bvd; }
        }
        s0 += __shfl_xor_sync(0xffffffffu, s0, 1);
        d0 += __shfl_xor_sync(0xffffffffu, d0, 1);
        s1 += __shfl_xor_sync(0xffffffffu, s1, 1);
        d1 += __shfl_xor_sync(0xffffffffu, d1, 1);
        int grow = m0 + r;
        if (half == 0 && grow < NN) {
            if (by == 0) g_att0[grow] = make_float4(s0, d0, s1, d1);
            else         g_att1[grow] = make_float2(s1, d1);
        }
    }
}

// ---------------- aggregation: single-pass softmax + fp16 gather ----------------
__global__ __launch_bounds__(128) void agg_kernel(const float* __restrict__ bias,
                                                  __half* __restrict__ oh,
                                                  float* __restrict__ of32,
                                                  int f32out)
{
    int i = blockIdx.x;
    int tid = threadIdx.x;
    int lane = tid & 31, warp = tid >> 5;

    __shared__ float w0[4], w1[4];
    __shared__ int   s_src[128];
    __shared__ float s_a0[128], s_a1[128];

    int s = g_off[i], e = g_off[i + 1];
    int d = e - s;
    float4 a0i = g_att0[i];
    float2 a1i = g_att1[i];
    float ed0 = a0i.y, ed1 = a0i.w + a1i.y;

    float acc0 = 0.f, acc1 = 0.f;
    int c0 = 2 * tid;
    bool act = (tid < HOUT);
    bool head0a = (c0 < HOUT);
    bool head0b = (c0 + 1 < HOUT);

    if (d <= 128) {
        bool valid = tid < d;
        int src = 0;
        float l0 = -1e30f, l1 = -1e30f;
        if (valid) {
            src = g_csr[s + tid];
            float4 b0 = g_att0[src]; float2 b1 = g_att1[src];
            l0 = leaky(b0.x + ed0);
            l1 = leaky(b0.z + b1.x + ed1);
        }
        float m0 = l0, m1 = l1;
#pragma unroll
        for (int o = 16; o; o >>= 1) {
            m0 = fmaxf(m0, __shfl_xor_sync(0xffffffffu, m0, o));
            m1 = fmaxf(m1, __shfl_xor_sync(0xffffffffu, m1, o));
        }
        if (lane == 0) { w0[warp] = m0; w1[warp] = m1; }
        __syncthreads();
        m0 = fmaxf(fmaxf(w0[0], w0[1]), fmaxf(w0[2], w0[3]));
        m1 = fmaxf(fmaxf(w1[0], w1[1]), fmaxf(w1[2], w1[3]));
        __syncthreads();

        float p0 = valid ? __expf(l0 - m0) : 0.f;
        float p1 = valid ? __expf(l1 - m1) : 0.f;
        float d0 = p0, d1 = p1;
#pragma unroll
        for (int o = 16; o; o >>= 1) {
            d0 += __shfl_xor_sync(0xffffffffu, d0, o);
            d1 += __shfl_xor_sync(0xffffffffu, d1, o);
        }
        if (lane == 0) { w0[warp] = d0; w1[warp] = d1; }
        __syncthreads();
        d0 = w0[0] + w0[1] + w0[2] + w0[3] + 1e-16f;
        d1 = w1[0] + w1[1] + w1[2] + w1[3] + 1e-16f;
        float r0 = 1.0f / d0, r1 = 1.0f / d1;

        s_src[tid] = src;
        s_a0[tid] = p0 * r0;
        s_a1[tid] = p1 * r1;
        __syncthreads();

        if (act) {
#pragma unroll 4
            for (int k = 0; k < d; k++) {
                int sk = s_src[k];
                __half2 hv2 = *(const __half2*)(g_hh + (size_t)sk * 256 + c0);
                float2 hv = __half22float2(hv2);
                float aa = head0a ? s_a0[k] : s_a1[k];
                float ab = head0b ? s_a0[k] : s_a1[k];
                acc0 += aa * hv.x;
                acc1 += ab * hv.y;
            }
        }
    } else {
        float m0 = -1e30f, m1 = -1e30f;
        for (int j = s + tid; j < e; j += 128) {
            int src = g_csr[j];
            float4 b0 = g_att0[src]; float2 b1 = g_att1[src];
            m0 = fmaxf(m0, leaky(b0.x + ed0));
            m1 = fmaxf(m1, leaky(b0.z + b1.x + ed1));
        }
#pragma unroll
        for (int o = 16; o; o >>= 1) {
            m0 = fmaxf(m0, __shfl_xor_sync(0xffffffffu, m0, o));
            m1 = fmaxf(m1, __shfl_xor_sync(0xffffffffu, m1, o));
        }
        if (lane == 0) { w0[warp] = m0; w1[warp] = m1; }
        __syncthreads();
        m0 = fmaxf(fmaxf(w0[0], w0[1]), fmaxf(w0[2], w0[3]));
        m1 = fmaxf(fmaxf(w1[0], w1[1]), fmaxf(w1[2], w1[3]));
        __syncthreads();

        float d0 = 0.f, d1 = 0.f;
        for (int j = s + tid; j < e; j += 128) {
            int src = g_csr[j];
            float4 b0 = g_att0[src]; float2 b1 = g_att1[src];
            d0 += __expf(leaky(b0.x + ed0) - m0);
            d1 += __expf(leaky(b0.z + b1.x + ed1) - m1);
        }
#pragma unroll
        for (int o = 16; o; o >>= 1) {
            d0 += __shfl_xor_sync(0xffffffffu, d0, o);
            d1 += __shfl_xor_sync(0xffffffffu, d1, o);
        }
        if (lane == 0) { w0[warp] = d0; w1[warp] = d1; }
        __syncthreads();
        d0 = w0[0] + w0[1] + w0[2] + w0[3] + 1e-16f;
        d1 = w1[0] + w1[1] + w1[2] + w1[3] + 1e-16f;
        float r0 = 1.0f / d0, r1 = 1.0f / d1;

        for (int base = s; base < e; base += 128) {
            int j = base + tid;
            if (j < e) {
                int src = g_csr[j];
                float4 b0 = g_att0[src]; float2 b1 = g_att1[src];
                s_src[tid] = src;
                s_a0[tid] = __expf(leaky(b0.x + ed0) - m0) * r0;
                s_a1[tid] = __expf(leaky(b0.z + b1.x + ed1) - m1) * r1;
            }
            __syncthreads();
            int cnt = min(128, e - base);
            if (act) {
#pragma unroll 4
                for (int k = 0; k < cnt; k++) {
                    int sk = s_src[k];
                    __half2 hv2 = *(const __half2*)(g_hh + (size_t)sk * 256 + c0);
                    float2 hv = __half22float2(hv2);
                    float aa = head0a ? s_a0[k] : s_a1[k];
                    float ab = head0b ? s_a0[k] : s_a1[k];
                    acc0 += aa * hv.x;
                    acc1 += ab * hv.y;
                }
            }
            __syncthreads();
        }
    }

    if (f32out) {
        if (act) {
            float v0 = fmaxf(acc0 + bias[c0], 0.f);
            float v1 = fmaxf(acc1 + bias[c0 + 1], 0.f);
            of32[(size_t)i * CHN + c0]     = v0;
            of32[(size_t)i * CHN + c0 + 1] = v1;
        }
    } else {
        size_t o = (size_t)i * KP2 + c0;
        if (act) {
            float v0 = fmaxf(acc0 + bias[c0], 0.f);
            float v1 = fmaxf(acc1 + bias[c0 + 1], 0.f);
            *(__half2*)(oh + o) = __floats2half2_rn(v0, v1);
        } else {
            *(__half2*)(oh + o) = __floats2half2_rn(0.f, 0.f);
        }
    }
}

// ---------------- fused pool + 4-layer MLP (one block per graph) ---------------
__global__ __launch_bounds__(256) void pool_mlp_kernel(
    const int* __restrict__ batch, const float* __restrict__ feat,
    const float* __restrict__ lw1, const float* __restrict__ lb1,
    const float* __restrict__ lw2, const float* __restrict__ lb2,
    const float* __restrict__ lw3, const float* __restrict__ lb3,
    const float* __restrict__ lw4, const float* __restrict__ lb4,
    float* __restrict__ out)
{
    int g = blockIdx.x;
    int tid = threadIdx.x;
    __shared__ int ss, se;
    __shared__ float sg[CHN], t1[200], t2[100], t3[100];

    if (tid == 0) {
        int lo = 0, hi = NN;
        while (lo < hi) { int mid = (lo + hi) >> 1; if (batch[mid] < g) lo = mid + 1; else hi = mid; }
        ss = lo;
        lo = 0; hi = NN;
        while (lo < hi) { int mid = (lo + hi) >> 1; if (batch[mid] < g + 1) lo = mid + 1; else hi = mid; }
        se = lo;
    }
    __syncthreads();
    if (tid < CHN) {
        float sum = 0.f;
        for (int i = ss; i < se; i++) sum += feat[(size_t)i * CHN + tid];
        sg[tid] = sum / fmaxf((float)(se - ss), 1.0f);
    }
    __syncthreads();
    if (tid < 200) {
        float s = lb1[tid];
        for (int k = 0; k < 250; k++) s += sg[k] * lw1[k * 200 + tid];
        t1[tid] = fmaxf(s, 0.f);
    }
    __syncthreads();
    if (tid < 100) {
        float s = lb2[tid];
        for (int k = 0; k < 200; k++) s += t1[k] * lw2[k * 100 + tid];
        t2[tid] = fmaxf(s, 0.f);
    }
    __syncthreads();
    if (tid < 100) {
        float s = lb3[tid];
        for (int k = 0; k < 100; k++) s += t2[k] * lw3[k * 100 + tid];
        t3[tid] = fmaxf(s, 0.f);
    }
    __syncthreads();
    if (tid < 29) {
        float s = lb4[tid];
        for (int k = 0; k < 100; k++) s += t3[k] * lw4[k * 29 + tid];
        out[g * 29 + tid] = s;
    }
}

// ---------------- driver --------------------------------------------------------
extern "C" void kernel_launch(void* const* d_in, const int* in_sizes, int n_in,
                              void* d_out, int out_size)
{
    const float* x     = (const float*)d_in[0];
    const int*   ei    = (const int*)d_in[1];
    const int*   batch = (const int*)d_in[2];
    const float* W[4]    = {(const float*)d_in[3],  (const float*)d_in[7],
                            (const float*)d_in[11], (const float*)d_in[15]};
    const float* Asrc[4] = {(const float*)d_in[4],  (const float*)d_in[8],
                            (const float*)d_in[12], (const float*)d_in[16]};
    const float* Adst[4] = {(const float*)d_in[5],  (const float*)d_in[9],
                            (const float*)d_in[13], (const float*)d_in[17]};
    const float* Bb[4]   = {(const float*)d_in[6],  (const float*)d_in[10],
                            (const float*)d_in[14], (const float*)d_in[18]};
    const float* lw1 = (const float*)d_in[19]; const float* lb1 = (const float*)d_in[20];
    const float* lw2 = (const float*)d_in[21]; const float* lb2 = (const float*)d_in[22];
    const float* lw3 = (const float*)d_in[23]; const float* lb3 = (const float*)d_in[24];
    const float* lw4 = (const float*)d_in[25]; const float* lb4 = (const float*)d_in[26];
    float* out = (float*)d_out;

    float *faP;
    __half *hhP, *a1hP, *a2hP, *whP;
    cudaGetSymbolAddress((void**)&hhP,  g_hh);
    cudaGetSymbolAddress((void**)&faP,  g_fa);
    cudaGetSymbolAddress((void**)&a1hP, g_a1h);
    cudaGetSymbolAddress((void**)&a2hP, g_a2h);
    cudaGetSymbolAddress((void**)&whP,  g_wh);

    cudaFuncSetAttribute(gemm_wmma_kernel,
                         cudaFuncAttributeMaxDynamicSharedMemorySize, GEMM_SMEM);

    init_kernel<<<(NN + 112 * KP2 + 255) / 256, 256>>>();
    count_kernel<<<(ET + 255) / 256, 256>>>(ei);
    scan_kernel<<<1, 1024>>>();
    scatter_kernel<<<(ET + 255) / 256, 256>>>(ei);

    split_a_kernel<<<(MPAD * KP1 + 255) / 256, 256>>>(x);
    split_w_all_kernel<<<(WTOTAL + 255) / 256, 256>>>(W[0], W[1], W[2], W[3]);

    dim3 ggrid(MPAD / MT2, 2);
    for (int l = 0; l < 4; l++) {
        const __half* Ain = (l == 0) ? a1hP : a2hP;
        int Kpad = (l == 0) ? KP1 : KP2;
        size_t woff = (l == 0) ? 0 : (size_t)WOFF1 + (size_t)(l - 1) * NT * KP2;
        gemm_wmma_kernel<<<ggrid, 256, GEMM_SMEM>>>(
            Ain, whP + woff, Kpad, Asrc[l], Adst[l], hhP);
        agg_kernel<<<NN, 128>>>(Bb[l], a2hP, faP, (l == 3) ? 1 : 0);
    }

    pool_mlp_kernel<<<GG, 256>>>(batch, faP, lw1, lb1, lw2, lb2, lw3, lb3, lw4, lb4, out);
}

// round 15
// speedup vs baseline: 1.0886x; 1.0546x over previous
#include <cuda_runtime.h>
#include <cuda_fp16.h>
#include <mma.h>
#include <cstdint>

using namespace nvcuda;

#define NN    10000
#define EE    320000
#define ET    330000
#define GG    100
#define CHN   250
#define HOUT  125
#define SLOPE 0.2f

#define MT2   64        // GEMM M tile
#define NT    256
#define MPAD  10112     // 158 * 64
#define KP1   384
#define KP2   256

// ---------------- scratch (zero-initialized at module load) --------------------
__device__ __half g_hh[MPAD * 256];          // GEMM output fp16 (gather source)
__device__ __half g_a2h[MPAD * 256];         // layers 2-4 A input fp16 (pad rows stay 0 forever)
__device__ float  g_fa[NN * CHN];            // layer-4 output fp32 (pool source)
__device__ float4 g_att0[NN];
__device__ float2 g_att1[NN];
__device__ int    g_cnt[NN];                 // zeroed at load; re-zeroed by scan_kernel
__device__ int    g_off[NN + 1];
__device__ int    g_pos[NN];
__device__ int    g_csr[ET];
__device__ __align__(256) __half g_a1h[MPAD * KP1];
#define WOFF1 (NT * KP1)
#define WTOTAL (NT * KP1 + 3 * NT * KP2)
__device__ __align__(256) __half g_wh[WTOTAL];

// ---------------- helpers ------------------------------------------------------
__device__ __forceinline__ uint32_t smem_u32(const void* p) {
    uint32_t a;
    asm("{ .reg .u64 t; cvta.to.shared.u64 t, %1; cvt.u32.u64 %0, t; }" : "=r"(a) : "l"(p));
    return a;
}
__device__ __forceinline__ void cp_async16(uint32_t dst, const void* src) {
    asm volatile("cp.async.cg.shared.global [%0], [%1], 16;" :: "r"(dst), "l"(src));
}
__device__ __forceinline__ void cp_commit() { asm volatile("cp.async.commit_group;" ::: "memory"); }
__device__ __forceinline__ void cp_wait1()  { asm volatile("cp.async.wait_group 1;" ::: "memory"); }
__device__ __forceinline__ float leaky(float x) { return x > 0.f ? x : SLOPE * x; }

// ---------------- CSR build (side branch) --------------------------------------
__global__ void count_kernel(const int* __restrict__ ei) {
    int i = blockIdx.x * blockDim.x + threadIdx.x;
    if (i >= ET) return;
    int dst = (i < EE) ? ei[EE + i] : (i - EE);
    atomicAdd(&g_cnt[dst], 1);
}
// scan also re-zeroes g_cnt so the next graph replay starts clean
__global__ void scan_kernel() {
    __shared__ int sp[1024];
    int t = threadIdx.x;
    int base = t * 10;
    int loc[10];
    int sum = 0;
#pragma unroll
    for (int i = 0; i < 10; i++) {
        int idx = base + i;
        int v = 0;
        if (idx < NN) { v = g_cnt[idx]; g_cnt[idx] = 0; }
        loc[i] = sum; sum += v;
    }
    sp[t] = sum;
    __syncthreads();
    for (int off = 1; off < 1024; off <<= 1) {
        int v = (t >= off) ? sp[t - off] : 0;
        __syncthreads();
        sp[t] += v;
        __syncthreads();
    }
    int pre = sp[t] - sum;
#pragma unroll
    for (int i = 0; i < 10; i++) {
        int idx = base + i;
        if (idx < NN) { int o = pre + loc[i]; g_off[idx] = o; g_pos[idx] = o; }
    }
    if (t == 1023) g_off[NN] = sp[1023];
}
__global__ void scatter_kernel(const int* __restrict__ ei) {
    int i = blockIdx.x * blockDim.x + threadIdx.x;
    if (i >= ET) return;
    int src, dst;
    if (i < EE) { src = ei[i]; dst = ei[EE + i]; }
    else        { src = i - EE; dst = i - EE; }
    int p = atomicAdd(&g_pos[dst], 1);
    g_csr[p] = src;
}

// ---------------- splits (main branch) ------------------------------------------
__global__ void split_a_kernel(const float* __restrict__ in) {
    int idx = blockIdx.x * blockDim.x + threadIdx.x;
    if (idx >= MPAD * KP1) return;
    int r = idx / KP1, k = idx - r * KP1;
    float v = (r < NN && k < 336) ? in[(size_t)r * 336 + k] : 0.f;
    g_a1h[idx] = __float2half(v);
}
__global__ void split_w_all_kernel(const float* __restrict__ W1, const float* __restrict__ W2,
                                   const float* __restrict__ W3, const float* __restrict__ W4)
{
    int idx = blockIdx.x * blockDim.x + threadIdx.x;
    if (idx >= WTOTAL) return;
    const float* W; int K, Kpad, rem;
    if (idx < NT * KP1) { W = W1; K = 336; Kpad = KP1; rem = idx; }
    else {
        int idx2 = idx - NT * KP1;
        int l = idx2 / (NT * KP2);
        rem = idx2 - l * (NT * KP2);
        W = (l == 0) ? W2 : (l == 1) ? W3 : W4;
        K = 250; Kpad = KP2;
    }
    int n = rem / Kpad, k = rem - n * Kpad;
    float v = (n < CHN && k < K) ? W[(size_t)k * CHN + n] : 0.f;
    g_wh[idx] = __float2half(v);
}

// ---------------- WMMA fp16 GEMM: 64x128 tile, 3-stage ring, 4 CTAs/SM ----------
#define ALD   40
#define BLD   40
#define A_ELE (64 * ALD)
#define B_ELE (128 * BLD)
#define STG_ELE (A_ELE + B_ELE)   // 7680 halves = 15360 B
#define CLD   136
#define GEMM_SMEM (3 * STG_ELE * 2)   // 46080 B

__global__ __launch_bounds__(256, 4) void gemm_wmma_kernel(
    const __half* __restrict__ Ain, const __half* __restrict__ Bin,
    int Kpad,
    const float* __restrict__ asrc, const float* __restrict__ adst,
    __half* __restrict__ hout)
{
    extern __shared__ char smem[];
    float* Cs = (float*)smem;
    __shared__ float s_as[128], s_ad[128];

    int tid = threadIdx.x;
    int wid = tid >> 5;
    int wm = wid >> 2, wn = wid & 3;
    int m0 = blockIdx.x * MT2;
    int by = blockIdx.y;
    int n0 = by * 128;

    if (tid < 128) {
        int col = n0 + tid;
        s_as[tid] = (col < CHN) ? asrc[col] : 0.f;
        s_ad[tid] = (col < CHN) ? adst[col] : 0.f;
    }

    uint32_t sbase = smem_u32(smem);
    int niter = Kpad >> 5;

    auto load_stage = [&](int st, int kb) {
        int kk = kb << 5;
        uint32_t stb = sbase + st * STG_ELE * 2;
        {
            int rowa = tid >> 2, grpa = tid & 3;
            cp_async16(stb + (rowa * ALD + grpa * 8) * 2,
                       Ain + (size_t)(m0 + rowa) * Kpad + kk + grpa * 8);
        }
#pragma unroll
        for (int i = 0; i < 2; i++) {
            int c = tid + i * 256;
            int rowb = c >> 2, grpb = c & 3;
            cp_async16(stb + (A_ELE + rowb * BLD + grpb * 8) * 2,
                       Bin + (size_t)(n0 + rowb) * Kpad + kk + grpb * 8);
        }
        cp_commit();
    };

    wmma::fragment<wmma::accumulator, 16, 16, 16, float> c[2][2];
#pragma unroll
    for (int i = 0; i < 2; i++)
#pragma unroll
        for (int j = 0; j < 2; j++) wmma::fill_fragment(c[i][j], 0.f);

    load_stage(0, 0);
    load_stage(1, 1);

    int slot = 0;
    for (int kb = 0; kb < niter; kb++) {
        cp_wait1();
        __syncthreads();
        int nslot = slot + 2; if (nslot >= 3) nslot -= 3;
        if (kb + 2 < niter) load_stage(nslot, kb + 2);
        else                cp_commit();

        const __half* stg = (const __half*)(smem + (size_t)slot * STG_ELE * 2);
        const __half* at = stg + wm * 32 * ALD;
        const __half* bt = stg + A_ELE + wn * 32 * BLD;
#pragma unroll
        for (int ks = 0; ks < 2; ks++) {
            wmma::fragment<wmma::matrix_a, 16, 16, 16, __half, wmma::row_major> a0, a1;
            wmma::load_matrix_sync(a0, at + ks * 16, ALD);
            wmma::load_matrix_sync(a1, at + 16 * ALD + ks * 16, ALD);
            wmma::fragment<wmma::matrix_b, 16, 16, 16, __half, wmma::col_major> b0, b1;
            wmma::load_matrix_sync(b0, bt + ks * 16, BLD);
            wmma::load_matrix_sync(b1, bt + 16 * BLD + ks * 16, BLD);
            wmma::mma_sync(c[0][0], a0, b0, c[0][0]);
            wmma::mma_sync(c[0][1], a0, b1, c[0][1]);
            wmma::mma_sync(c[1][0], a1, b0, c[1][0]);
            wmma::mma_sync(c[1][1], a1, b1, c[1][1]);
        }
        slot = (slot + 1 == 3) ? 0 : slot + 1;
    }
    __syncthreads();

#pragma unroll
    for (int i = 0; i < 2; i++)
#pragma unroll
        for (int j = 0; j < 2; j++)
            wmma::store_matrix_sync(Cs + (wm * 32 + i * 16) * CLD + wn * 32 + j * 16,
                                    c[i][j], CLD, wmma::mem_row_major);
    __syncthreads();

#pragma unroll
    for (int it = 0; it < 16; it++) {
        int idx = it * 256 + tid;
        int r = idx >> 6, c2 = idx & 63;
        int grow = m0 + r, gcol = n0 + 2 * c2;
        if (grow < NN && gcol < CHN) {
            float v0 = Cs[r * CLD + 2 * c2];
            float v1 = Cs[r * CLD + 2 * c2 + 1];
            *(__half2*)(hout + (size_t)grow * 256 + gcol) = __floats2half2_rn(v0, v1);
        }
    }

    if (tid < 128) {
        int r = tid >> 1;
        int half = tid & 1;
        int ccb = half * 64;
        float s0 = 0.f, d0 = 0.f, s1 = 0.f, d1 = 0.f;
#pragma unroll 8
        for (int q = 0; q < 64; q++) {
            int cc = ccb + q;
            float v = Cs[r * CLD + cc];
            float a = s_as[cc], bvd = s_ad[cc];
            if (n0 + cc < HOUT) { s0 += v * a; d0 += v * bvd; }
            else                { s1 += v * a; d1 += v * bvd; }
        }
        s0 += __shfl_xor_sync(0xffffffffu, s0, 1);
        d0 += __shfl_xor_sync(0xffffffffu, d0, 1);
        s1 += __shfl_xor_sync(0xffffffffu, s1, 1);
        d1 += __shfl_xor_sync(0xffffffffu, d1, 1);
        int grow = m0 + r;
        if (half == 0 && grow < NN) {
            if (by == 0) g_att0[grow] = make_float4(s0, d0, s1, d1);
            else         g_att1[grow] = make_float2(s1, d1);
        }
    }
}

// ---------------- aggregation: single-pass softmax + fp16 gather ----------------
__global__ __launch_bounds__(128) void agg_kernel(const float* __restrict__ bias,
                                                  __half* __restrict__ oh,
                                                  float* __restrict__ of32,
                                                  int f32out)
{
    int i = blockIdx.x;
    int tid = threadIdx.x;
    int lane = tid & 31, warp = tid >> 5;

    __shared__ float w0[4], w1[4];
    __shared__ int   s_src[128];
    __shared__ float s_a0[128], s_a1[128];

    int s = g_off[i], e = g_off[i + 1];
    int d = e - s;
    float4 a0i = g_att0[i];
    float2 a1i = g_att1[i];
    float ed0 = a0i.y, ed1 = a0i.w + a1i.y;

    float acc0 = 0.f, acc1 = 0.f;
    int c0 = 2 * tid;
    bool act = (tid < HOUT);
    bool head0a = (c0 < HOUT);
    bool head0b = (c0 + 1 < HOUT);

    if (d <= 128) {
        bool valid = tid < d;
        int src = 0;
        float l0 = -1e30f, l1 = -1e30f;
        if (valid) {
            src = g_csr[s + tid];
            float4 b0 = g_att0[src]; float2 b1 = g_att1[src];
            l0 = leaky(b0.x + ed0);
            l1 = leaky(b0.z + b1.x + ed1);
        }
        float m0 = l0, m1 = l1;
#pragma unroll
        for (int o = 16; o; o >>= 1) {
            m0 = fmaxf(m0, __shfl_xor_sync(0xffffffffu, m0, o));
            m1 = fmaxf(m1, __shfl_xor_sync(0xffffffffu, m1, o));
        }
        if (lane == 0) { w0[warp] = m0; w1[warp] = m1; }
        __syncthreads();
        m0 = fmaxf(fmaxf(w0[0], w0[1]), fmaxf(w0[2], w0[3]));
        m1 = fmaxf(fmaxf(w1[0], w1[1]), fmaxf(w1[2], w1[3]));
        __syncthreads();

        float p0 = valid ? __expf(l0 - m0) : 0.f;
        float p1 = valid ? __expf(l1 - m1) : 0.f;
        float d0 = p0, d1 = p1;
#pragma unroll
        for (int o = 16; o; o >>= 1) {
            d0 += __shfl_xor_sync(0xffffffffu, d0, o);
            d1 += __shfl_xor_sync(0xffffffffu, d1, o);
        }
        if (lane == 0) { w0[warp] = d0; w1[warp] = d1; }
        __syncthreads();
        d0 = w0[0] + w0[1] + w0[2] + w0[3] + 1e-16f;
        d1 = w1[0] + w1[1] + w1[2] + w1[3] + 1e-16f;
        float r0 = 1.0f / d0, r1 = 1.0f / d1;

        s_src[tid] = src;
        s_a0[tid] = p0 * r0;
        s_a1[tid] = p1 * r1;
        __syncthreads();

        if (act) {
#pragma unroll 4
            for (int k = 0; k < d; k++) {
                int sk = s_src[k];
                __half2 hv2 = *(const __half2*)(g_hh + (size_t)sk * 256 + c0);
                float2 hv = __half22float2(hv2);
                float aa = head0a ? s_a0[k] : s_a1[k];
                float ab = head0b ? s_a0[k] : s_a1[k];
                acc0 += aa * hv.x;
                acc1 += ab * hv.y;
            }
        }
    } else {
        float m0 = -1e30f, m1 = -1e30f;
        for (int j = s + tid; j < e; j += 128) {
            int src = g_csr[j];
            float4 b0 = g_att0[src]; float2 b1 = g_att1[src];
            m0 = fmaxf(m0, leaky(b0.x + ed0));
            m1 = fmaxf(m1, leaky(b0.z + b1.x + ed1));
        }
#pragma unroll
        for (int o = 16; o; o >>= 1) {
            m0 = fmaxf(m0, __shfl_xor_sync(0xffffffffu, m0, o));
            m1 = fmaxf(m1, __shfl_xor_sync(0xffffffffu, m1, o));
        }
        if (lane == 0) { w0[warp] = m0; w1[warp] = m1; }
        __syncthreads();
        m0 = fmaxf(fmaxf(w0[0], w0[1]), fmaxf(w0[2], w0[3]));
        m1 = fmaxf(fmaxf(w1[0], w1[1]), fmaxf(w1[2], w1[3]));
        __syncthreads();

        float d0 = 0.f, d1 = 0.f;
        for (int j = s + tid; j < e; j += 128) {
            int src = g_csr[j];
            float4 b0 = g_att0[src]; float2 b1 = g_att1[src];
            d0 += __expf(leaky(b0.x + ed0) - m0);
            d1 += __expf(leaky(b0.z + b1.x + ed1) - m1);
        }
#pragma unroll
        for (int o = 16; o; o >>= 1) {
            d0 += __shfl_xor_sync(0xffffffffu, d0, o);
            d1 += __shfl_xor_sync(0xffffffffu, d1, o);
        }
        if (lane == 0) { w0[warp] = d0; w1[warp] = d1; }
        __syncthreads();
        d0 = w0[0] + w0[1] + w0[2] + w0[3] + 1e-16f;
        d1 = w1[0] + w1[1] + w1[2] + w1[3] + 1e-16f;
        float r0 = 1.0f / d0, r1 = 1.0f / d1;

        for (int base = s; base < e; base += 128) {
            int j = base + tid;
            if (j < e) {
                int src = g_csr[j];
                float4 b0 = g_att0[src]; float2 b1 = g_att1[src];
                s_src[tid] = src;
                s_a0[tid] = __expf(leaky(b0.x + ed0) - m0) * r0;
                s_a1[tid] = __expf(leaky(b0.z + b1.x + ed1) - m1) * r1;
            }
            __syncthreads();
            int cnt = min(128, e - base);
            if (act) {
#pragma unroll 4
                for (int k = 0; k < cnt; k++) {
                    int sk = s_src[k];
                    __half2 hv2 = *(const __half2*)(g_hh + (size_t)sk * 256 + c0);
                    float2 hv = __half22float2(hv2);
                    float aa = head0a ? s_a0[k] : s_a1[k];
                    float ab = head0b ? s_a0[k] : s_a1[k];
                    acc0 += aa * hv.x;
                    acc1 += ab * hv.y;
                }
            }
            __syncthreads();
        }
    }

    if (f32out) {
        if (act) {
            float v0 = fmaxf(acc0 + bias[c0], 0.f);
            float v1 = fmaxf(acc1 + bias[c0 + 1], 0.f);
            of32[(size_t)i * CHN + c0]     = v0;
            of32[(size_t)i * CHN + c0 + 1] = v1;
        }
    } else {
        size_t o = (size_t)i * KP2 + c0;
        if (act) {
            float v0 = fmaxf(acc0 + bias[c0], 0.f);
            float v1 = fmaxf(acc1 + bias[c0 + 1], 0.f);
            *(__half2*)(oh + o) = __floats2half2_rn(v0, v1);
        } else {
            *(__half2*)(oh + o) = __floats2half2_rn(0.f, 0.f);
        }
    }
}

// ---------------- fused pool + 4-layer MLP (one block per graph) ---------------
__global__ __launch_bounds__(256) void pool_mlp_kernel(
    const int* __restrict__ batch, const float* __restrict__ feat,
    const float* __restrict__ lw1, const float* __restrict__ lb1,
    const float* __restrict__ lw2, const float* __restrict__ lb2,
    const float* __restrict__ lw3, const float* __restrict__ lb3,
    const float* __restrict__ lw4, const float* __restrict__ lb4,
    float* __restrict__ out)
{
    int g = blockIdx.x;
    int tid = threadIdx.x;
    __shared__ int ss, se;
    __shared__ float sg[CHN], t1[200], t2[100], t3[100];

    if (tid == 0) {
        int lo = 0, hi = NN;
        while (lo < hi) { int mid = (lo + hi) >> 1; if (batch[mid] < g) lo = mid + 1; else hi = mid; }
        ss = lo;
        lo = 0; hi = NN;
        while (lo < hi) { int mid = (lo + hi) >> 1; if (batch[mid] < g + 1) lo = mid + 1; else hi = mid; }
        se = lo;
    }
    __syncthreads();
    if (tid < CHN) {
        float sum = 0.f;
        for (int i = ss; i < se; i++) sum += feat[(size_t)i * CHN + tid];
        sg[tid] = sum / fmaxf((float)(se - ss), 1.0f);
    }
    __syncthreads();
    if (tid < 200) {
        float s = lb1[tid];
        for (int k = 0; k < 250; k++) s += sg[k] * lw1[k * 200 + tid];
        t1[tid] = fmaxf(s, 0.f);
    }
    __syncthreads();
    if (tid < 100) {
        float s = lb2[tid];
        for (int k = 0; k < 200; k++) s += t1[k] * lw2[k * 100 + tid];
        t2[tid] = fmaxf(s, 0.f);
    }
    __syncthreads();
    if (tid < 100) {
        float s = lb3[tid];
        for (int k = 0; k < 100; k++) s += t2[k] * lw3[k * 100 + tid];
        t3[tid] = fmaxf(s, 0.f);
    }
    __syncthreads();
    if (tid < 29) {
        float s = lb4[tid];
        for (int k = 0; k < 100; k++) s += t3[k] * lw4[k * 29 + tid];
        out[g * 29 + tid] = s;
    }
}

// ---------------- driver --------------------------------------------------------
extern "C" void kernel_launch(void* const* d_in, const int* in_sizes, int n_in,
                              void* d_out, int out_size)
{
    const float* x     = (const float*)d_in[0];
    const int*   ei    = (const int*)d_in[1];
    const int*   batch = (const int*)d_in[2];
    const float* W[4]    = {(const float*)d_in[3],  (const float*)d_in[7],
                            (const float*)d_in[11], (const float*)d_in[15]};
    const float* Asrc[4] = {(const float*)d_in[4],  (const float*)d_in[8],
                            (const float*)d_in[12], (const float*)d_in[16]};
    const float* Adst[4] = {(const float*)d_in[5],  (const float*)d_in[9],
                            (const float*)d_in[13], (const float*)d_in[17]};
    const float* Bb[4]   = {(const float*)d_in[6],  (const float*)d_in[10],
                            (const float*)d_in[14], (const float*)d_in[18]};
    const float* lw1 = (const float*)d_in[19]; const float* lb1 = (const float*)d_in[20];
    const float* lw2 = (const float*)d_in[21]; const float* lb2 = (const float*)d_in[22];
    const float* lw3 = (const float*)d_in[23]; const float* lb3 = (const float*)d_in[24];
    const float* lw4 = (const float*)d_in[25]; const float* lb4 = (const float*)d_in[26];
    float* out = (float*)d_out;

    float *faP;
    __half *hhP, *a1hP, *a2hP, *whP;
    cudaGetSymbolAddress((void**)&hhP,  g_hh);
    cudaGetSymbolAddress((void**)&faP,  g_fa);
    cudaGetSymbolAddress((void**)&a1hP, g_a1h);
    cudaGetSymbolAddress((void**)&a2hP, g_a2h);
    cudaGetSymbolAddress((void**)&whP,  g_wh);

    cudaFuncSetAttribute(gemm_wmma_kernel,
                         cudaFuncAttributeMaxDynamicSharedMemorySize, GEMM_SMEM);

    // ---- fork: CSR build runs on a side stream, parallel to splits + gemm1 ----
    cudaStream_t s2;
    cudaStreamCreateWithFlags(&s2, cudaStreamNonBlocking);
    cudaEvent_t evFork, evJoin;
    cudaEventCreateWithFlags(&evFork, cudaEventDisableTiming);
    cudaEventCreateWithFlags(&evJoin, cudaEventDisableTiming);

    cudaEventRecord(evFork, 0);
    cudaStreamWaitEvent(s2, evFork, 0);
    count_kernel<<<(ET + 255) / 256, 256, 0, s2>>>(ei);
    scan_kernel<<<1, 1024, 0, s2>>>();
    scatter_kernel<<<(ET + 255) / 256, 256, 0, s2>>>(ei);
    cudaEventRecord(evJoin, s2);

    // main branch: splits + layer-1 GEMM (independent of CSR)
    split_a_kernel<<<(MPAD * KP1 + 255) / 256, 256>>>(x);
    split_w_all_kernel<<<(WTOTAL + 255) / 256, 256>>>(W[0], W[1], W[2], W[3]);

    dim3 ggrid(MPAD / MT2, 2);
    gemm_wmma_kernel<<<ggrid, 256, GEMM_SMEM>>>(
        a1hP, whP, KP1, Asrc[0], Adst[0], hhP);

    // join before first aggregation (needs CSR)
    cudaStreamWaitEvent(0, evJoin, 0);
    agg_kernel<<<NN, 128>>>(Bb[0], a2hP, faP, 0);

    for (int l = 1; l < 4; l++) {
        size_t woff = (size_t)WOFF1 + (size_t)(l - 1) * NT * KP2;
        gemm_wmma_kernel<<<ggrid, 256, GEMM_SMEM>>>(
            a2hP, whP + woff, KP2, Asrc[l], Adst[l], hhP);
        agg_kernel<<<NN, 128>>>(Bb[l], a2hP, faP, (l == 3) ? 1 : 0);
    }

    pool_mlp_kernel<<<GG, 256>>>(batch, faP, lw1, lb1, lw2, lb2, lw3, lb3, lw4, lb4, out);
}